// round 13
// baseline (speedup 1.0000x reference)
#include <cuda_runtime.h>
#include <cuda_fp16.h>
#include <cstdint>

// ---------------- scratch (device globals) ----------------
__device__ float g_K1p[1024 * 4096];
__device__ float g_K2p[1024 * 4096];
__device__ float g_K3p[1024 * 4096];
__device__ __half g_K1x[1024 * 2048];
__device__ __half g_K2x[1024 * 2048];
__device__ __half g_K3x[1024 * 2048];
__device__ __half g_K1h[1024 * 2048];
__device__ __half g_K2h[1024 * 2048];
__device__ __half g_K3h[1024 * 2048];
__device__ __half g_K1hb[1024 * 2048];
__device__ __half g_K2hb[1024 * 2048];
__device__ __half g_K3hb[1024 * 2048];
// weights fp16: plain, -(W+Wi), (W-Wi) for kernel + recurrent
__device__ __half g_Wr [2048 * 6144];
__device__ __half g_Rr [2048 * 6144];
__device__ __half g_Wnn[2048 * 6144];
__device__ __half g_Rnn[2048 * 6144];
__device__ __half g_Wdd[2048 * 6144];
__device__ __half g_Rdd[2048 * 6144];
// activations fp16: halves + sums (compact [1024 x 2048])
__device__ __half g_X1[1024 * 2048];
__device__ __half g_X2[1024 * 2048];
__device__ __half g_XS[1024 * 2048];
__device__ __half g_H1[1024 * 2048];
__device__ __half g_H2[1024 * 2048];
__device__ __half g_HS[1024 * 2048];
__device__ __half g_R1[1024 * 2048];
__device__ __half g_R2[1024 * 2048];
__device__ __half g_RS[1024 * 2048];

__device__ __forceinline__ uint32_t s2u(const void* p) {
    uint32_t a;
    asm("{ .reg .u64 t; cvta.to.shared.u64 t, %1; cvt.u32.u64 %0, t; }" : "=r"(a) : "l"(p));
    return a;
}

#define CP_ASYNC16(dst, src) \
    asm volatile("cp.async.cg.shared.global [%0], [%1], 16;" :: "r"(dst), "l"(src))
#define CP_COMMIT() asm volatile("cp.async.commit_group;" ::: "memory")
#define CP_WAIT1()  asm volatile("cp.async.wait_group 1;" ::: "memory")
#define CP_WAIT0()  asm volatile("cp.async.wait_group 0;" ::: "memory")

#define SW(o) ((o) ^ (((o) >> 3) & 0x70))

#define LDSM4(r, a) \
    asm volatile("ldmatrix.sync.aligned.m8n8.x4.shared.b16 {%0,%1,%2,%3}, [%4];" \
        : "=r"((r)[0]), "=r"((r)[1]), "=r"((r)[2]), "=r"((r)[3]) : "r"(a))
#define LDSMT4(r, a) \
    asm volatile("ldmatrix.sync.aligned.m8n8.x4.trans.shared.b16 {%0,%1,%2,%3}, [%4];" \
        : "=r"((r)[0]), "=r"((r)[1]), "=r"((r)[2]), "=r"((r)[3]) : "r"(a))

#define MMA16(acc, a, b0, b1) \
    asm volatile("mma.sync.aligned.m16n8k16.row.col.f32.f16.f16.f32 " \
        "{%0,%1,%2,%3},{%4,%5,%6,%7},{%8,%9},{%0,%1,%2,%3};" \
        : "+f"((acc)[0]), "+f"((acc)[1]), "+f"((acc)[2]), "+f"((acc)[3]) \
        : "r"((a)[0]), "r"((a)[1]), "r"((a)[2]), "r"((a)[3]), "r"(b0), "r"(b1))

#define STAGE      32768
#define SM_B_OFF   16384
#define NSTAGE     3
#define SMEM_TOTAL (NSTAGE * STAGE)

// problem descriptor: C = sgn*(A @ B[wcol..]) + bias, K = ktn*64
struct GP {
    const __half *A0, *A1;
    const __half *B0, *B1;
    const float  *bias;
    void         *C;           // float* or __half* per hout
    int wcol, ktn, ldC;
    float sgn;
    int hout;                  // 1 = store fp16
};
struct GP6 {
    GP  p[6];
    int yb[5];
};

// ---------------------------------------------------------------------------
// generic fp16 GEMM, fp32 accum; up to 6 problems per launch selected by
// blockIdx.y ranges. 256 thr, 8 warps, CTA 128x128, warp 64x32, 3-stage
// cp.async pipeline, double-buffered A fragments, 2 CTAs/SM.
// ---------------------------------------------------------------------------
__global__ void __launch_bounds__(256, 2) gemm_g(GP6 P)
{
    extern __shared__ char smem[];
    const uint32_t sb = s2u(smem);

    const int tid  = threadIdx.x;
    const int lane = tid & 31;
    const int warp = tid >> 5;
    const int wm   = warp >> 2;
    const int wn   = warp & 3;
    const int bm   = blockIdx.x;
    const int by   = blockIdx.y;

    int idx = 0;
    #pragma unroll
    for (int q = 0; q < 5; q++)
        if (by >= P.yb[q]) idx = q + 1;
    const int bn = by - (idx ? P.yb[idx - 1] : 0);

    const __half* A0 = P.p[idx].A0;
    const __half* A1 = P.p[idx].A1;
    const __half* B0 = P.p[idx].B0;
    const __half* B1 = P.p[idx].B1;
    const int wcol = P.p[idx].wcol;
    const int KT   = P.p[idx].ktn;

    float acc[4][4][4];
    #pragma unroll
    for (int i = 0; i < 4; i++)
        #pragma unroll
        for (int j = 0; j < 4; j++)
            #pragma unroll
            for (int k = 0; k < 4; k++) acc[i][j][k] = 0.f;

    const int arow = tid >> 1;
    const int ac0  = (tid & 1) * 4;
    const int brow = tid >> 2;
    const int bc0  = (tid & 3) * 4;
    const size_t mBase = (size_t)(bm * 128);
    const int    gn    = wcol + bn * 128;

    const uint32_t xorv = (lane & 7) << 4;
    const uint32_t l87  = (lane & 7) + ((lane >> 3) & 1) * 8;
    const uint32_t aRowOff = (wm * 64 + l87) * 128;
    const uint32_t bRowOff = SM_B_OFF + (wn >> 1) * 8192 +
                             ((lane >> 3) * 8 + (lane & 7)) * 128;
    const uint32_t p16c = (lane >> 4) * 16;
    const uint32_t bsel = (wn & 1) * 64;

#define CP_STAGE(KT_IDX)                                                            \
    do {                                                                            \
        const int kg = (KT_IDX) * 64;                                               \
        const int klocal = kg & 2047;                                               \
        const uint32_t sbase = sb + ((KT_IDX) % NSTAGE) * STAGE;                    \
        const __half* Ap = (kg >= 2048) ? A1 : A0;                                  \
        const __half* asrc = Ap + (mBase + arow) * 2048 + klocal + ac0 * 8;         \
        _Pragma("unroll")                                                           \
        for (int i = 0; i < 4; i++)                                                 \
            CP_ASYNC16(sbase + SW(arow * 128 + (ac0 + i) * 16), asrc + i * 8);      \
        const __half* Bp = (kg >= 2048) ? B1 : B0;                                  \
        const __half* bsrc = Bp + (size_t)(klocal + brow) * 6144 + gn;              \
        _Pragma("unroll")                                                           \
        for (int i = 0; i < 4; i++) {                                               \
            const int ch = bc0 + i, pp = ch >> 3, cc = ch & 7;                      \
            CP_ASYNC16(sbase + SM_B_OFF + pp * 8192 + SW(brow * 128 + cc * 16),     \
                       bsrc + pp * 64 + cc * 8);                                    \
        }                                                                           \
        CP_COMMIT();                                                                \
    } while (0)

#define LDA(dst, BASE, S)                                                           \
    do {                                                                            \
        const uint32_t off = ((uint32_t)((S) * 32) + p16c) ^ xorv;                  \
        _Pragma("unroll")                                                           \
        for (int mf = 0; mf < 4; mf++)                                              \
            LDSM4((dst)[mf], (BASE) + aRowOff + mf * 2048 + off);                   \
    } while (0)

#define LDB(dst, BASE, KH)                                                          \
    do {                                                                            \
        _Pragma("unroll")                                                           \
        for (int nf = 0; nf < 4; nf++)                                              \
            LDSMT4((dst)[nf], (BASE) + bRowOff + (KH) * 4096 +                      \
                   (((uint32_t)(bsel + nf * 16)) ^ xorv));                          \
    } while (0)

    uint32_t afr[2][4][4];
    uint32_t bfr[4][4];

    CP_STAGE(0);
    CP_STAGE(1);
    CP_WAIT1();
    __syncthreads();

    for (int kt = 0; kt < KT; ++kt) {
        const uint32_t base = sb + (kt % NSTAGE) * STAGE;

        LDA(afr[0], base, 0);
        if (kt + 2 < KT) CP_STAGE(kt + 2);

        #pragma unroll
        for (int s = 0; s < 4; s++) {
            if ((s & 1) == 0) LDB(bfr, base, s >> 1);
            if (s < 3) LDA(afr[(s + 1) & 1], base, s + 1);
            const int sh = s & 1;
            #pragma unroll
            for (int mf = 0; mf < 4; mf++)
                #pragma unroll
                for (int nf = 0; nf < 4; nf++)
                    MMA16(acc[mf][nf], afr[s & 1][mf],
                          bfr[nf][sh * 2], bfr[nf][sh * 2 + 1]);
        }

        if (kt + 1 < KT) {
            if (kt + 2 < KT) CP_WAIT1(); else CP_WAIT0();
            __syncthreads();
        }
    }

    // epilogue: C = sgn*acc + bias (fp32 or fp16 output)
    const float* bias = P.p[idx].bias;
    const int    ldC  = P.p[idx].ldC;
    const float  sg   = P.p[idx].sgn;
    const int    hout = P.p[idx].hout;
    float*  Cf = (float*)P.p[idx].C;
    __half* Ch = (__half*)P.p[idx].C;

    const int gid = lane >> 2;
    const int tig = lane & 3;
    #pragma unroll
    for (int mf = 0; mf < 4; mf++) {
        const int row = bm * 128 + wm * 64 + mf * 16 + gid;
        #pragma unroll
        for (int nf = 0; nf < 4; nf++) {
            const int col = bn * 128 + wn * 32 + nf * 8 + tig * 2;
            float b0 = 0.f, b1 = 0.f;
            if (bias) { b0 = bias[col]; b1 = bias[col + 1]; }
            float v00 = sg * acc[mf][nf][0] + b0, v01 = sg * acc[mf][nf][1] + b1;
            float v10 = sg * acc[mf][nf][2] + b0, v11 = sg * acc[mf][nf][3] + b1;
            if (hout) {
                *(__half2*)(Ch + (size_t)row       * ldC + col) = __floats2half2_rn(v00, v01);
                *(__half2*)(Ch + (size_t)(row + 8) * ldC + col) = __floats2half2_rn(v10, v11);
            } else {
                *(float2*)(Cf + (size_t)row       * ldC + col) = make_float2(v00, v01);
                *(float2*)(Cf + (size_t)(row + 8) * ldC + col) = make_float2(v10, v11);
            }
        }
    }
#undef CP_STAGE
#undef LDA
#undef LDB
}

// ---------------- elementwise ----------------
__device__ __forceinline__ float hsig(float x) {
    return fminf(fmaxf(fmaf(0.2f, x, 0.5f), 0.f), 1.f);
}
__device__ __forceinline__ uint2 pack4(float a, float b, float c, float d) {
    __half2 lo = __floats2half2_rn(a, b);
    __half2 hi = __floats2half2_rn(c, d);
    uint2 o;
    o.x = *(uint32_t*)&lo;
    o.y = *(uint32_t*)&hi;
    return o;
}
__device__ __forceinline__ float4 ld4h(const __half* p, size_t o) {
    uint2 u = *(const uint2*)(p + o);
    __half2 a = *(__half2*)&u.x, b = *(__half2*)&u.y;
    float2 fa = __half22float2(a), fb = __half22float2(b);
    return make_float4(fa.x, fa.y, fb.x, fb.y);
}

// fused prep: y=0 weight combos (12288 blocks), y=1 activations (4096 blocks)
__global__ void k_prep(const float4* __restrict__ rk,  const float4* __restrict__ ik,
                       const float4* __restrict__ rrk, const float4* __restrict__ irk,
                       uint2* __restrict__ Wr,  uint2* __restrict__ Rr,
                       uint2* __restrict__ Wnn, uint2* __restrict__ Rnn,
                       uint2* __restrict__ Wdd, uint2* __restrict__ Rdd,
                       const float* __restrict__ x, const float* __restrict__ h,
                       __half* __restrict__ X1, __half* __restrict__ X2, __half* __restrict__ XS,
                       __half* __restrict__ H1, __half* __restrict__ H2, __half* __restrict__ HS)
{
    if (blockIdx.y == 0) {
        int i = blockIdx.x * blockDim.x + threadIdx.x;
        float4 a = rk[i], b = ik[i];
        Wr[i]  = pack4(a.x, a.y, a.z, a.w);
        Wnn[i] = pack4(-(a.x + b.x), -(a.y + b.y), -(a.z + b.z), -(a.w + b.w));
        Wdd[i] = pack4(a.x - b.x, a.y - b.y, a.z - b.z, a.w - b.w);
        float4 c = rrk[i], d = irk[i];
        Rr[i]  = pack4(c.x, c.y, c.z, c.w);
        Rnn[i] = pack4(-(c.x + d.x), -(c.y + d.y), -(c.z + d.z), -(c.w + d.w));
        Rdd[i] = pack4(c.x - d.x, c.y - d.y, c.z - d.z, c.w - d.w);
    } else {
        int bx = blockIdx.x;
        if (bx >= 4096) return;
        const float* in = (bx >= 2048) ? h : x;
        __half *o1 = (bx >= 2048) ? H1 : X1;
        __half *o2 = (bx >= 2048) ? H2 : X2;
        __half *os = (bx >= 2048) ? HS : XS;
        int i4 = (bx & 2047) * blockDim.x + threadIdx.x;
        int idx = i4 * 4;
        int m = idx >> 11, j = idx & 2047;
        float4 v1 = *(const float4*)(in + (size_t)m * 4096 + j);
        float4 v2 = *(const float4*)(in + (size_t)m * 4096 + 2048 + j);
        *(uint2*)(o1 + idx) = pack4(v1.x, v1.y, v1.z, v1.w);
        *(uint2*)(o2 + idx) = pack4(v2.x, v2.y, v2.z, v2.w);
        *(uint2*)(os + idx) = pack4(v1.x + v2.x, v1.y + v2.y, v1.z + v2.z, v1.w + v2.w);
    }
}

// rh halves + sum. rR = hsig(K1p + K3p)[r cols], rI = hsig(K1p + K2p)[r cols]
__global__ void k_rh(const float* __restrict__ h,
                     const float* __restrict__ K1p, const float* __restrict__ K2p,
                     const float* __restrict__ K3p,
                     __half* __restrict__ R1, __half* __restrict__ R2, __half* __restrict__ RS)
{
    int i4 = blockIdx.x * blockDim.x + threadIdx.x;
    int idx = i4 * 4;
    int m = idx >> 11, j = idx & 2047;
    size_t o = (size_t)m * 4096 + 2048 + j;
    float4 k1 = *(const float4*)(K1p + o);
    float4 k2 = *(const float4*)(K2p + o);
    float4 k3 = *(const float4*)(K3p + o);
    float4 h1 = *(const float4*)(h + (size_t)m * 4096 + j);
    float4 h2 = *(const float4*)(h + (size_t)m * 4096 + 2048 + j);
    float a1 = hsig(k1.x + k3.x) * h1.x, b1 = hsig(k1.y + k3.y) * h1.y,
          c1 = hsig(k1.z + k3.z) * h1.z, d1 = hsig(k1.w + k3.w) * h1.w;
    float a2 = hsig(k1.x + k2.x) * h2.x, b2 = hsig(k1.y + k2.y) * h2.y,
          c2 = hsig(k1.z + k2.z) * h2.z, d2 = hsig(k1.w + k2.w) * h2.w;
    *(uint2*)(R1 + idx) = pack4(a1, b1, c1, d1);
    *(uint2*)(R2 + idx) = pack4(a2, b2, c2, d2);
    *(uint2*)(RS + idx) = pack4(a1 + a2, b1 + b2, c1 + c2, d1 + d2);
}

// h_out = z*h + (1-z)*tanh(Xh + Hh); Hh = sum of split-K halves (fp16 inputs)
__global__ void k_final(const float* __restrict__ h,
                        const float* __restrict__ K1p, const float* __restrict__ K2p,
                        const float* __restrict__ K3p,
                        const __half* __restrict__ K1x, const __half* __restrict__ K2x,
                        const __half* __restrict__ K3x,
                        const __half* __restrict__ K1h, const __half* __restrict__ K2h,
                        const __half* __restrict__ K3h,
                        const __half* __restrict__ K1hb, const __half* __restrict__ K2hb,
                        const __half* __restrict__ K3hb,
                        float* __restrict__ out)
{
    int i4 = blockIdx.x * blockDim.x + threadIdx.x;
    int idx = i4 * 4;
    int m  = idx >> 12;
    int j  = idx & 4095;
    int jj = j & 2047;
    size_t op = (size_t)m * 4096 + jj;
    size_t oc = (size_t)m * 2048 + jj;
    float4 k1  = *(const float4*)(K1p + op);
    float4 x1  = ld4h(K1x, oc);
    float4 h1a = ld4h(K1h, oc);
    float4 h1b = ld4h(K1hb, oc);
    float4 kv, xv, hva, hvb;
    if (j < 2048) {
        kv  = *(const float4*)(K3p + op);
        xv  = ld4h(K3x, oc);
        hva = ld4h(K3h, oc);
        hvb = ld4h(K3hb, oc);
    } else {
        kv  = *(const float4*)(K2p + op);
        xv  = ld4h(K2x, oc);
        hva = ld4h(K2h, oc);
        hvb = ld4h(K2hb, oc);
    }
    float4 hv = *(const float4*)(h + idx);
    float4 o;
    float z, t;
    z = hsig(k1.x + kv.x); t = tanhf(x1.x + xv.x + h1a.x + h1b.x + hva.x + hvb.x);
    o.x = z * hv.x + (1.f - z) * t;
    z = hsig(k1.y + kv.y); t = tanhf(x1.y + xv.y + h1a.y + h1b.y + hva.y + hvb.y);
    o.y = z * hv.y + (1.f - z) * t;
    z = hsig(k1.z + kv.z); t = tanhf(x1.z + xv.z + h1a.z + h1b.z + hva.z + hvb.z);
    o.z = z * hv.z + (1.f - z) * t;
    z = hsig(k1.w + kv.w); t = tanhf(x1.w + xv.w + h1a.w + h1b.w + hva.w + hvb.w);
    o.w = z * hv.w + (1.f - z) * t;
    *(float4*)(out + idx) = o;
}

// ---------------- launch ----------------
extern "C" void kernel_launch(void* const* d_in, const int* in_sizes, int n_in,
                              void* d_out, int out_size)
{
    const float* inputs = (const float*)d_in[0];
    const float* h      = (const float*)d_in[1];
    const float* rk     = (const float*)d_in[2];
    const float* ik     = (const float*)d_in[3];
    const float* rrk    = (const float*)d_in[4];
    const float* irk    = (const float*)d_in[5];
    const float* rb     = (const float*)d_in[6];
    const float* ib     = (const float*)d_in[7];
    float* out = (float*)d_out;

    float *K1p, *K2p, *K3p;
    __half *K1x, *K2x, *K3x, *K1h, *K2h, *K3h, *K1hb, *K2hb, *K3hb;
    __half *Wr, *Rr, *Wnn, *Rnn, *Wdd, *Rdd;
    __half *X1, *X2, *XS, *H1, *H2, *HS, *R1, *R2, *RS;
    cudaGetSymbolAddress((void**)&K1p, g_K1p);
    cudaGetSymbolAddress((void**)&K2p, g_K2p);
    cudaGetSymbolAddress((void**)&K3p, g_K3p);
    cudaGetSymbolAddress((void**)&K1x, g_K1x);
    cudaGetSymbolAddress((void**)&K2x, g_K2x);
    cudaGetSymbolAddress((void**)&K3x, g_K3x);
    cudaGetSymbolAddress((void**)&K1h, g_K1h);
    cudaGetSymbolAddress((void**)&K2h, g_K2h);
    cudaGetSymbolAddress((void**)&K3h, g_K3h);
    cudaGetSymbolAddress((void**)&K1hb, g_K1hb);
    cudaGetSymbolAddress((void**)&K2hb, g_K2hb);
    cudaGetSymbolAddress((void**)&K3hb, g_K3hb);
    cudaGetSymbolAddress((void**)&Wr,  g_Wr);
    cudaGetSymbolAddress((void**)&Rr,  g_Rr);
    cudaGetSymbolAddress((void**)&Wnn, g_Wnn);
    cudaGetSymbolAddress((void**)&Rnn, g_Rnn);
    cudaGetSymbolAddress((void**)&Wdd, g_Wdd);
    cudaGetSymbolAddress((void**)&Rdd, g_Rdd);
    cudaGetSymbolAddress((void**)&X1,  g_X1);
    cudaGetSymbolAddress((void**)&X2,  g_X2);
    cudaGetSymbolAddress((void**)&XS,  g_XS);
    cudaGetSymbolAddress((void**)&H1,  g_H1);
    cudaGetSymbolAddress((void**)&H2,  g_H2);
    cudaGetSymbolAddress((void**)&HS,  g_HS);
    cudaGetSymbolAddress((void**)&R1,  g_R1);
    cudaGetSymbolAddress((void**)&R2,  g_R2);
    cudaGetSymbolAddress((void**)&RS,  g_RS);

    cudaFuncSetAttribute(gemm_g, cudaFuncAttributeMaxDynamicSharedMemorySize, SMEM_TOTAL);

    // fused prep (weights + activations in one launch)
    k_prep<<<dim3(12288, 2), 256>>>((const float4*)rk, (const float4*)ik,
                                    (const float4*)rrk, (const float4*)irk,
                                    (uint2*)Wr, (uint2*)Rr, (uint2*)Wnn,
                                    (uint2*)Rnn, (uint2*)Wdd, (uint2*)Rdd,
                                    inputs, h, X1, X2, XS, H1, H2, HS);

    // G1: all x/h GEMMs in ONE launch (6 problems, long-K first).
    {
        GP6 P;
        P.p[0] = {XS, HS, Wr,  Rr,  nullptr,    K1p, 0,    64, 4096,  1.f, 0};
        P.p[1] = {X1, H1, Wnn, Rnn, ib,         K2p, 0,    64, 4096,  1.f, 0};
        P.p[2] = {X2, H2, Wdd, Rdd, rb,         K3p, 0,    64, 4096, -1.f, 0};
        P.p[3] = {XS, XS, Wr,  Wr,  nullptr,    K1x, 4096, 32, 2048,  1.f, 1};
        P.p[4] = {X1, X1, Wnn, Wnn, ib + 4096,  K2x, 4096, 32, 2048,  1.f, 1};
        P.p[5] = {X2, X2, Wdd, Wdd, rb + 4096,  K3x, 4096, 32, 2048, -1.f, 1};
        P.yb[0] = 32; P.yb[1] = 64; P.yb[2] = 96; P.yb[3] = 112; P.yb[4] = 128;
        gemm_g<<<dim3(8, 144), 256, SMEM_TOTAL>>>(P);
    }

    // rh halves + sum
    k_rh<<<2048, 256>>>(h, K1p, K2p, K3p, R1, R2, RS);

    // G2: Hh GEMMs split-K x2 (6 problems of K=1024 each), fp16 outputs.
    {
        const size_t bo = (size_t)1024 * 6144;
        GP6 P;
        P.p[0] = {RS,          RS, Rr,        Rr,  nullptr, K1h,  4096, 16, 2048,  1.f, 1};
        P.p[1] = {RS + 1024,   RS, Rr  + bo,  Rr,  nullptr, K1hb, 4096, 16, 2048,  1.f, 1};
        P.p[2] = {R1,          R1, Rnn,       Rnn, nullptr, K2h,  4096, 16, 2048,  1.f, 1};
        P.p[3] = {R1 + 1024,   R1, Rnn + bo,  Rnn, nullptr, K2hb, 4096, 16, 2048,  1.f, 1};
        P.p[4] = {R2,          R2, Rdd,       Rdd, nullptr, K3h,  4096, 16, 2048, -1.f, 1};
        P.p[5] = {R2 + 1024,   R2, Rdd + bo,  Rdd, nullptr, K3hb, 4096, 16, 2048, -1.f, 1};
        P.yb[0] = 16; P.yb[1] = 32; P.yb[2] = 48; P.yb[3] = 64; P.yb[4] = 80;
        gemm_g<<<dim3(8, 96), 256, SMEM_TOTAL>>>(P);
    }

    // combine
    k_final<<<4096, 256>>>(h, K1p, K2p, K3p, K1x, K2x, K3x,
                           K1h, K2h, K3h, K1hb, K2hb, K3hb, out);
}

// round 15
// speedup vs baseline: 1.0281x; 1.0281x over previous
#include <cuda_runtime.h>
#include <cuda_fp16.h>
#include <cstdint>

// ---------------- scratch (device globals) ----------------
__device__ float g_K1p[1024 * 4096];
__device__ float g_K2p[1024 * 4096];
__device__ float g_K3p[1024 * 4096];
__device__ float g_K1x[1024 * 2048];
__device__ float g_K2x[1024 * 2048];
__device__ float g_K3x[1024 * 2048];
__device__ float g_K1h[1024 * 2048];
__device__ float g_K2h[1024 * 2048];
__device__ float g_K3h[1024 * 2048];
__device__ float g_K1hb[1024 * 2048];
__device__ float g_K2hb[1024 * 2048];
__device__ float g_K3hb[1024 * 2048];
// weights fp16: plain, -(W+Wi), (W-Wi) for kernel + recurrent
__device__ __half g_Wr [2048 * 6144];
__device__ __half g_Rr [2048 * 6144];
__device__ __half g_Wnn[2048 * 6144];
__device__ __half g_Rnn[2048 * 6144];
__device__ __half g_Wdd[2048 * 6144];
__device__ __half g_Rdd[2048 * 6144];
// activations fp16: halves + sums (compact [1024 x 2048])
__device__ __half g_X1[1024 * 2048];
__device__ __half g_X2[1024 * 2048];
__device__ __half g_XS[1024 * 2048];
__device__ __half g_H1[1024 * 2048];
__device__ __half g_H2[1024 * 2048];
__device__ __half g_HS[1024 * 2048];
__device__ __half g_R1[1024 * 2048];
__device__ __half g_R2[1024 * 2048];
__device__ __half g_RS[1024 * 2048];

__device__ __forceinline__ uint32_t s2u(const void* p) {
    uint32_t a;
    asm("{ .reg .u64 t; cvta.to.shared.u64 t, %1; cvt.u32.u64 %0, t; }" : "=r"(a) : "l"(p));
    return a;
}

#define CP_ASYNC16(dst, src) \
    asm volatile("cp.async.cg.shared.global [%0], [%1], 16;" :: "r"(dst), "l"(src))
#define CP_COMMIT() asm volatile("cp.async.commit_group;" ::: "memory")
#define CP_WAIT1()  asm volatile("cp.async.wait_group 1;" ::: "memory")
#define CP_WAIT0()  asm volatile("cp.async.wait_group 0;" ::: "memory")

#define SW(o) ((o) ^ (((o) >> 3) & 0x70))

#define LDSM4(r, a) \
    asm volatile("ldmatrix.sync.aligned.m8n8.x4.shared.b16 {%0,%1,%2,%3}, [%4];" \
        : "=r"((r)[0]), "=r"((r)[1]), "=r"((r)[2]), "=r"((r)[3]) : "r"(a))
#define LDSMT4(r, a) \
    asm volatile("ldmatrix.sync.aligned.m8n8.x4.trans.shared.b16 {%0,%1,%2,%3}, [%4];" \
        : "=r"((r)[0]), "=r"((r)[1]), "=r"((r)[2]), "=r"((r)[3]) : "r"(a))

#define MMA16(acc, a, b0, b1) \
    asm volatile("mma.sync.aligned.m16n8k16.row.col.f32.f16.f16.f32 " \
        "{%0,%1,%2,%3},{%4,%5,%6,%7},{%8,%9},{%0,%1,%2,%3};" \
        : "+f"((acc)[0]), "+f"((acc)[1]), "+f"((acc)[2]), "+f"((acc)[3]) \
        : "r"((a)[0]), "r"((a)[1]), "r"((a)[2]), "r"((a)[3]), "r"(b0), "r"(b1))

#define STAGE      32768
#define SM_B_OFF   16384
#define NSTAGE     3
#define SMEM_TOTAL (NSTAGE * STAGE)

// problem descriptor: C = sgn*(A @ B[wcol..]) + bias, K = ktn*64
struct GP {
    const __half *A0, *A1;
    const __half *B0, *B1;
    const float  *bias;
    float        *C;
    int wcol, ktn, ldC;
    float sgn;
};
struct GP6 {
    GP  p[6];
    int yb[5];
};

// ---------------------------------------------------------------------------
// generic fp16 GEMM, fp32 accum; up to 6 problems per launch selected by
// blockIdx.y ranges. 256 thr, 8 warps, CTA 128x128, warp 64x32, 3-stage
// cp.async pipeline, double-buffered B fragments, 2 CTAs/SM.
// ---------------------------------------------------------------------------
__global__ void __launch_bounds__(256, 2) gemm_g(GP6 P)
{
    extern __shared__ char smem[];
    const uint32_t sb = s2u(smem);

    const int tid  = threadIdx.x;
    const int lane = tid & 31;
    const int warp = tid >> 5;
    const int wm   = warp >> 2;
    const int wn   = warp & 3;
    const int bm   = blockIdx.x;
    const int by   = blockIdx.y;

    int idx = 0;
    #pragma unroll
    for (int q = 0; q < 5; q++)
        if (by >= P.yb[q]) idx = q + 1;
    const int bn = by - (idx ? P.yb[idx - 1] : 0);

    const __half* A0 = P.p[idx].A0;
    const __half* A1 = P.p[idx].A1;
    const __half* B0 = P.p[idx].B0;
    const __half* B1 = P.p[idx].B1;
    const int wcol = P.p[idx].wcol;
    const int KT   = P.p[idx].ktn;

    float acc[4][4][4];
    #pragma unroll
    for (int i = 0; i < 4; i++)
        #pragma unroll
        for (int j = 0; j < 4; j++)
            #pragma unroll
            for (int k = 0; k < 4; k++) acc[i][j][k] = 0.f;

    const int arow = tid >> 1;
    const int ac0  = (tid & 1) * 4;
    const int brow = tid >> 2;
    const int bc0  = (tid & 3) * 4;
    const size_t mBase = (size_t)(bm * 128);
    const int    gn    = wcol + bn * 128;

    const uint32_t xorv = (lane & 7) << 4;
    const uint32_t l87  = (lane & 7) + ((lane >> 3) & 1) * 8;
    const uint32_t aRowOff = (wm * 64 + l87) * 128;
    const uint32_t bRowOff = SM_B_OFF + (wn >> 1) * 8192 +
                             ((lane >> 3) * 8 + (lane & 7)) * 128;
    const uint32_t p16c = (lane >> 4) * 16;
    const uint32_t bsel = (wn & 1) * 64;

#define CP_STAGE(KT_IDX)                                                            \
    do {                                                                            \
        const int kg = (KT_IDX) * 64;                                               \
        const int klocal = kg & 2047;                                               \
        const uint32_t sbase = sb + ((KT_IDX) % NSTAGE) * STAGE;                    \
        const __half* Ap = (kg >= 2048) ? A1 : A0;                                  \
        const __half* asrc = Ap + (mBase + arow) * 2048 + klocal + ac0 * 8;         \
        _Pragma("unroll")                                                           \
        for (int i = 0; i < 4; i++)                                                 \
            CP_ASYNC16(sbase + SW(arow * 128 + (ac0 + i) * 16), asrc + i * 8);      \
        const __half* Bp = (kg >= 2048) ? B1 : B0;                                  \
        const __half* bsrc = Bp + (size_t)(klocal + brow) * 6144 + gn;              \
        _Pragma("unroll")                                                           \
        for (int i = 0; i < 4; i++) {                                               \
            const int ch = bc0 + i, pp = ch >> 3, cc = ch & 7;                      \
            CP_ASYNC16(sbase + SM_B_OFF + pp * 8192 + SW(brow * 128 + cc * 16),     \
                       bsrc + pp * 64 + cc * 8);                                    \
        }                                                                           \
        CP_COMMIT();                                                                \
    } while (0)

#define LDA(dst, BASE, S)                                                           \
    do {                                                                            \
        const uint32_t off = ((uint32_t)((S) * 32) + p16c) ^ xorv;                  \
        _Pragma("unroll")                                                           \
        for (int mf = 0; mf < 4; mf++)                                              \
            LDSM4((dst)[mf], (BASE) + aRowOff + mf * 2048 + off);                   \
    } while (0)

#define LDB(dst, BASE, KH)                                                          \
    do {                                                                            \
        _Pragma("unroll")                                                           \
        for (int nf = 0; nf < 4; nf++)                                              \
            LDSMT4((dst)[nf], (BASE) + bRowOff + (KH) * 4096 +                      \
                   (((uint32_t)(bsel + nf * 16)) ^ xorv));                          \
    } while (0)

    uint32_t afr[4][4];
    uint32_t bfr[2][4][4];     // double-buffered across k32 pairs

    CP_STAGE(0);
    CP_STAGE(1);
    CP_WAIT1();
    __syncthreads();

    for (int kt = 0; kt < KT; ++kt) {
        const uint32_t base = sb + (kt % NSTAGE) * STAGE;

        LDB(bfr[0], base, 0);               // pair 0, hidden behind CP_STAGE issue
        if (kt + 2 < KT) CP_STAGE(kt + 2);

        #pragma unroll
        for (int s = 0; s < 4; s++) {
            if (s == 0) LDB(bfr[1], base, 1);   // prefetch pair 1 during pair 0
            LDA(afr, base, s);                  // just-in-time A
            const int pr = s >> 1;              // which bfr buffer
            const int sh = s & 1;               // k16 step within pair
            #pragma unroll
            for (int mf = 0; mf < 4; mf++)
                #pragma unroll
                for (int nf = 0; nf < 4; nf++)
                    MMA16(acc[mf][nf], afr[mf],
                          bfr[pr][nf][sh * 2], bfr[pr][nf][sh * 2 + 1]);
        }

        if (kt + 1 < KT) {
            if (kt + 2 < KT) CP_WAIT1(); else CP_WAIT0();
            __syncthreads();
        }
    }

    // epilogue: C = sgn*acc + bias
    const float* bias = P.p[idx].bias;
    float*       C    = P.p[idx].C;
    const int    ldC  = P.p[idx].ldC;
    const float  sg   = P.p[idx].sgn;

    const int gid = lane >> 2;
    const int tig = lane & 3;
    #pragma unroll
    for (int mf = 0; mf < 4; mf++) {
        const int row = bm * 128 + wm * 64 + mf * 16 + gid;
        #pragma unroll
        for (int nf = 0; nf < 4; nf++) {
            const int col = bn * 128 + wn * 32 + nf * 8 + tig * 2;
            float b0 = 0.f, b1 = 0.f;
            if (bias) { b0 = bias[col]; b1 = bias[col + 1]; }
            float2 v0 = make_float2(sg * acc[mf][nf][0] + b0, sg * acc[mf][nf][1] + b1);
            float2 v1 = make_float2(sg * acc[mf][nf][2] + b0, sg * acc[mf][nf][3] + b1);
            *(float2*)(C + (size_t)row       * ldC + col) = v0;
            *(float2*)(C + (size_t)(row + 8) * ldC + col) = v1;
        }
    }
#undef CP_STAGE
#undef LDA
#undef LDB
}

// ---------------- elementwise ----------------
__device__ __forceinline__ float hsig(float x) {
    return fminf(fmaxf(fmaf(0.2f, x, 0.5f), 0.f), 1.f);
}
__device__ __forceinline__ uint2 pack4(float a, float b, float c, float d) {
    __half2 lo = __floats2half2_rn(a, b);
    __half2 hi = __floats2half2_rn(c, d);
    uint2 o;
    o.x = *(uint32_t*)&lo;
    o.y = *(uint32_t*)&hi;
    return o;
}

// fused prep: y=0 weight combos (12288 blocks), y=1 activations (4096 blocks)
__global__ void k_prep(const float4* __restrict__ rk,  const float4* __restrict__ ik,
                       const float4* __restrict__ rrk, const float4* __restrict__ irk,
                       uint2* __restrict__ Wr,  uint2* __restrict__ Rr,
                       uint2* __restrict__ Wnn, uint2* __restrict__ Rnn,
                       uint2* __restrict__ Wdd, uint2* __restrict__ Rdd,
                       const float* __restrict__ x, const float* __restrict__ h,
                       __half* __restrict__ X1, __half* __restrict__ X2, __half* __restrict__ XS,
                       __half* __restrict__ H1, __half* __restrict__ H2, __half* __restrict__ HS)
{
    if (blockIdx.y == 0) {
        int i = blockIdx.x * blockDim.x + threadIdx.x;
        float4 a = rk[i], b = ik[i];
        Wr[i]  = pack4(a.x, a.y, a.z, a.w);
        Wnn[i] = pack4(-(a.x + b.x), -(a.y + b.y), -(a.z + b.z), -(a.w + b.w));
        Wdd[i] = pack4(a.x - b.x, a.y - b.y, a.z - b.z, a.w - b.w);
        float4 c = rrk[i], d = irk[i];
        Rr[i]  = pack4(c.x, c.y, c.z, c.w);
        Rnn[i] = pack4(-(c.x + d.x), -(c.y + d.y), -(c.z + d.z), -(c.w + d.w));
        Rdd[i] = pack4(c.x - d.x, c.y - d.y, c.z - d.z, c.w - d.w);
    } else {
        int bx = blockIdx.x;
        if (bx >= 4096) return;
        const float* in = (bx >= 2048) ? h : x;
        __half *o1 = (bx >= 2048) ? H1 : X1;
        __half *o2 = (bx >= 2048) ? H2 : X2;
        __half *os = (bx >= 2048) ? HS : XS;
        int i4 = (bx & 2047) * blockDim.x + threadIdx.x;
        int idx = i4 * 4;
        int m = idx >> 11, j = idx & 2047;
        float4 v1 = *(const float4*)(in + (size_t)m * 4096 + j);
        float4 v2 = *(const float4*)(in + (size_t)m * 4096 + 2048 + j);
        *(uint2*)(o1 + idx) = pack4(v1.x, v1.y, v1.z, v1.w);
        *(uint2*)(o2 + idx) = pack4(v2.x, v2.y, v2.z, v2.w);
        *(uint2*)(os + idx) = pack4(v1.x + v2.x, v1.y + v2.y, v1.z + v2.z, v1.w + v2.w);
    }
}

// rh halves + sum. rR = hsig(K1p + K3p)[r cols], rI = hsig(K1p + K2p)[r cols]
__global__ void k_rh(const float* __restrict__ h,
                     const float* __restrict__ K1p, const float* __restrict__ K2p,
                     const float* __restrict__ K3p,
                     __half* __restrict__ R1, __half* __restrict__ R2, __half* __restrict__ RS)
{
    int i4 = blockIdx.x * blockDim.x + threadIdx.x;
    int idx = i4 * 4;
    int m = idx >> 11, j = idx & 2047;
    size_t o = (size_t)m * 4096 + 2048 + j;
    float4 k1 = *(const float4*)(K1p + o);
    float4 k2 = *(const float4*)(K2p + o);
    float4 k3 = *(const float4*)(K3p + o);
    float4 h1 = *(const float4*)(h + (size_t)m * 4096 + j);
    float4 h2 = *(const float4*)(h + (size_t)m * 4096 + 2048 + j);
    float a1 = hsig(k1.x + k3.x) * h1.x, b1 = hsig(k1.y + k3.y) * h1.y,
          c1 = hsig(k1.z + k3.z) * h1.z, d1 = hsig(k1.w + k3.w) * h1.w;
    float a2 = hsig(k1.x + k2.x) * h2.x, b2 = hsig(k1.y + k2.y) * h2.y,
          c2 = hsig(k1.z + k2.z) * h2.z, d2 = hsig(k1.w + k2.w) * h2.w;
    *(uint2*)(R1 + idx) = pack4(a1, b1, c1, d1);
    *(uint2*)(R2 + idx) = pack4(a2, b2, c2, d2);
    *(uint2*)(RS + idx) = pack4(a1 + a2, b1 + b2, c1 + c2, d1 + d2);
}

// h_out = z*h + (1-z)*tanh(Xh + Hh); Hh = sum of split-K halves
__global__ void k_final(const float* __restrict__ h,
                        const float* __restrict__ K1p, const float* __restrict__ K2p,
                        const float* __restrict__ K3p,
                        const float* __restrict__ K1x, const float* __restrict__ K2x,
                        const float* __restrict__ K3x,
                        const float* __restrict__ K1h, const float* __restrict__ K2h,
                        const float* __restrict__ K3h,
                        const float* __restrict__ K1hb, const float* __restrict__ K2hb,
                        const float* __restrict__ K3hb,
                        float* __restrict__ out)
{
    int i4 = blockIdx.x * blockDim.x + threadIdx.x;
    int idx = i4 * 4;
    int m  = idx >> 12;
    int j  = idx & 4095;
    int jj = j & 2047;
    size_t op = (size_t)m * 4096 + jj;
    size_t oc = (size_t)m * 2048 + jj;
    float4 k1  = *(const float4*)(K1p + op);
    float4 x1  = *(const float4*)(K1x + oc);
    float4 h1a = *(const float4*)(K1h + oc);
    float4 h1b = *(const float4*)(K1hb + oc);
    float4 kv, xv, hva, hvb;
    if (j < 2048) {
        kv  = *(const float4*)(K3p + op);
        xv  = *(const float4*)(K3x + oc);
        hva = *(const float4*)(K3h + oc);
        hvb = *(const float4*)(K3hb + oc);
    } else {
        kv  = *(const float4*)(K2p + op);
        xv  = *(const float4*)(K2x + oc);
        hva = *(const float4*)(K2h + oc);
        hvb = *(const float4*)(K2hb + oc);
    }
    float4 hv = *(const float4*)(h + idx);
    float4 o;
    float z, t;
    z = hsig(k1.x + kv.x); t = tanhf(x1.x + xv.x + h1a.x + h1b.x + hva.x + hvb.x);
    o.x = z * hv.x + (1.f - z) * t;
    z = hsig(k1.y + kv.y); t = tanhf(x1.y + xv.y + h1a.y + h1b.y + hva.y + hvb.y);
    o.y = z * hv.y + (1.f - z) * t;
    z = hsig(k1.z + kv.z); t = tanhf(x1.z + xv.z + h1a.z + h1b.z + hva.z + hvb.z);
    o.z = z * hv.z + (1.f - z) * t;
    z = hsig(k1.w + kv.w); t = tanhf(x1.w + xv.w + h1a.w + h1b.w + hva.w + hvb.w);
    o.w = z * hv.w + (1.f - z) * t;
    *(float4*)(out + idx) = o;
}

// ---------------- launch ----------------
extern "C" void kernel_launch(void* const* d_in, const int* in_sizes, int n_in,
                              void* d_out, int out_size)
{
    const float* inputs = (const float*)d_in[0];
    const float* h      = (const float*)d_in[1];
    const float* rk     = (const float*)d_in[2];
    const float* ik     = (const float*)d_in[3];
    const float* rrk    = (const float*)d_in[4];
    const float* irk    = (const float*)d_in[5];
    const float* rb     = (const float*)d_in[6];
    const float* ib     = (const float*)d_in[7];
    float* out = (float*)d_out;

    float *K1p, *K2p, *K3p, *K1x, *K2x, *K3x, *K1h, *K2h, *K3h, *K1hb, *K2hb, *K3hb;
    __half *Wr, *Rr, *Wnn, *Rnn, *Wdd, *Rdd;
    __half *X1, *X2, *XS, *H1, *H2, *HS, *R1, *R2, *RS;
    cudaGetSymbolAddress((void**)&K1p, g_K1p);
    cudaGetSymbolAddress((void**)&K2p, g_K2p);
    cudaGetSymbolAddress((void**)&K3p, g_K3p);
    cudaGetSymbolAddress((void**)&K1x, g_K1x);
    cudaGetSymbolAddress((void**)&K2x, g_K2x);
    cudaGetSymbolAddress((void**)&K3x, g_K3x);
    cudaGetSymbolAddress((void**)&K1h, g_K1h);
    cudaGetSymbolAddress((void**)&K2h, g_K2h);
    cudaGetSymbolAddress((void**)&K3h, g_K3h);
    cudaGetSymbolAddress((void**)&K1hb, g_K1hb);
    cudaGetSymbolAddress((void**)&K2hb, g_K2hb);
    cudaGetSymbolAddress((void**)&K3hb, g_K3hb);
    cudaGetSymbolAddress((void**)&Wr,  g_Wr);
    cudaGetSymbolAddress((void**)&Rr,  g_Rr);
    cudaGetSymbolAddress((void**)&Wnn, g_Wnn);
    cudaGetSymbolAddress((void**)&Rnn, g_Rnn);
    cudaGetSymbolAddress((void**)&Wdd, g_Wdd);
    cudaGetSymbolAddress((void**)&Rdd, g_Rdd);
    cudaGetSymbolAddress((void**)&X1,  g_X1);
    cudaGetSymbolAddress((void**)&X2,  g_X2);
    cudaGetSymbolAddress((void**)&XS,  g_XS);
    cudaGetSymbolAddress((void**)&H1,  g_H1);
    cudaGetSymbolAddress((void**)&H2,  g_H2);
    cudaGetSymbolAddress((void**)&HS,  g_HS);
    cudaGetSymbolAddress((void**)&R1,  g_R1);
    cudaGetSymbolAddress((void**)&R2,  g_R2);
    cudaGetSymbolAddress((void**)&RS,  g_RS);

    cudaFuncSetAttribute(gemm_g, cudaFuncAttributeMaxDynamicSharedMemorySize, SMEM_TOTAL);

    // fused prep (weights + activations in one launch)
    k_prep<<<dim3(12288, 2), 256>>>((const float4*)rk, (const float4*)ik,
                                    (const float4*)rrk, (const float4*)irk,
                                    (uint2*)Wr, (uint2*)Rr, (uint2*)Wnn,
                                    (uint2*)Rnn, (uint2*)Wdd, (uint2*)Rdd,
                                    inputs, h, X1, X2, XS, H1, H2, HS);

    // G1: all x/h GEMMs in ONE launch (6 problems, long-K first).
    {
        GP6 P;
        P.p[0] = {XS, HS, Wr,  Rr,  nullptr,    K1p, 0,    64, 4096,  1.f};
        P.p[1] = {X1, H1, Wnn, Rnn, ib,         K2p, 0,    64, 4096,  1.f};
        P.p[2] = {X2, H2, Wdd, Rdd, rb,         K3p, 0,    64, 4096, -1.f};
        P.p[3] = {XS, XS, Wr,  Wr,  nullptr,    K1x, 4096, 32, 2048,  1.f};
        P.p[4] = {X1, X1, Wnn, Wnn, ib + 4096,  K2x, 4096, 32, 2048,  1.f};
        P.p[5] = {X2, X2, Wdd, Wdd, rb + 4096,  K3x, 4096, 32, 2048, -1.f};
        P.yb[0] = 32; P.yb[1] = 64; P.yb[2] = 96; P.yb[3] = 112; P.yb[4] = 128;
        gemm_g<<<dim3(8, 144), 256, SMEM_TOTAL>>>(P);
    }

    // rh halves + sum
    k_rh<<<2048, 256>>>(h, K1p, K2p, K3p, R1, R2, RS);

    // G2: Hh GEMMs split-K x2 (6 problems of K=1024 each).
    {
        const size_t bo = (size_t)1024 * 6144;
        GP6 P;
        P.p[0] = {RS,          RS, Rr,        Rr,  nullptr, K1h,  4096, 16, 2048,  1.f};
        P.p[1] = {RS + 1024,   RS, Rr  + bo,  Rr,  nullptr, K1hb, 4096, 16, 2048,  1.f};
        P.p[2] = {R1,          R1, Rnn,       Rnn, nullptr, K2h,  4096, 16, 2048,  1.f};
        P.p[3] = {R1 + 1024,   R1, Rnn + bo,  Rnn, nullptr, K2hb, 4096, 16, 2048,  1.f};
        P.p[4] = {R2,          R2, Rdd,       Rdd, nullptr, K3h,  4096, 16, 2048, -1.f};
        P.p[5] = {R2 + 1024,   R2, Rdd + bo,  Rdd, nullptr, K3hb, 4096, 16, 2048, -1.f};
        P.yb[0] = 16; P.yb[1] = 32; P.yb[2] = 48; P.yb[3] = 64; P.yb[4] = 80;
        gemm_g<<<dim3(8, 96), 256, SMEM_TOTAL>>>(P);
    }

    // combine
    k_final<<<4096, 256>>>(h, K1p, K2p, K3p, K1x, K2x, K3x,
                           K1h, K2h, K3h, K1hb, K2hb, K3hb, out);
}